// round 7
// baseline (speedup 1.0000x reference)
#include <cuda_runtime.h>
#include <cuda_fp16.h>
#include <cstdint>

// Problem constants
#define NROWS   4096
#define INFEAT  4096
#define OUTFEAT 4096
#define NCODE   256
#define KLEAF   16
#define KGLOB   4096
// Aggregation tiling
#define TO      128
#define TN      256
#define THREADS 512
#define CCH     8
#define NCHUNK  (NCODE / CCH)      // 32
#define BUFB    32768              // bytes per staging buffer
#define AGG_SMEM (2 * BUFB)        // 64 KB

// Static device scratch
__device__ __align__(16) unsigned char g_codes[NROWS * NCODE];          // 1 MB
__device__ __align__(16) __half        g_lutT[(size_t)KGLOB * OUTFEAT]; // 32 MB [k][o]

// ---------------------------------------------------------------- helpers
__device__ __forceinline__ uint32_t smem_u32(const void* p) {
    uint32_t a;
    asm("{ .reg .u64 t; cvta.to.shared.u64 t, %1; cvt.u32.u64 %0, t; }"
        : "=r"(a) : "l"(p));
    return a;
}
__device__ __forceinline__ void cp_async16(uint32_t s, const void* g) {
    asm volatile("cp.async.cg.shared.global [%0], [%1], 16;"
                 :: "r"(s), "l"(g) : "memory");
}
__device__ __forceinline__ void cp_commit() {
    asm volatile("cp.async.commit_group;" ::: "memory");
}
__device__ __forceinline__ void cp_wait0() {
    asm volatile("cp.async.wait_group 0;" ::: "memory");
}
__device__ __forceinline__ void cp_wait1() {
    asm volatile("cp.async.wait_group 1;" ::: "memory");
}

// ---------------------------------------------------------------- encode
__global__ void __launch_bounds__(NCODE) encode_kernel(
    const float* __restrict__ input,
    const int*   __restrict__ dims,
    const float* __restrict__ thr)
{
    const int n = blockIdx.x;
    const int c = threadIdx.x;
    const int4 d4 = *reinterpret_cast<const int4*>(dims + c * 4);
    const float* row = input + (size_t)n * INFEAT;
    const float x0 = __ldg(row + d4.x);
    const float x1 = __ldg(row + d4.y);
    const float x2 = __ldg(row + d4.z);
    const float x3 = __ldg(row + d4.w);
    const float* t = thr + c * 15;
    int i = 1;
    i = 2 * i + (x0 > __ldg(t + i - 1) ? 1 : 0);
    i = 2 * i + (x1 > __ldg(t + i - 1) ? 1 : 0);
    i = 2 * i + (x2 > __ldg(t + i - 1) ? 1 : 0);
    i = 2 * i + (x3 > __ldg(t + i - 1) ? 1 : 0);
    g_codes[n * NCODE + c] = (unsigned char)(i - 16);
}

// ---------------------------------------------------------------- transpose
// g_lutT[k][o] = half(lut[o][k])
__global__ void __launch_bounds__(256) transpose_kernel(
    const float* __restrict__ lut)
{
    __shared__ __half tile[64][66];

    const int k0 = blockIdx.x * 64;
    const int o0 = blockIdx.y * 64;
    const int tid = threadIdx.x;

#pragma unroll
    for (int j = 0; j < 16; ++j) {
        const int flat = j * 256 + tid;
        const int o = flat >> 6;
        const int k = flat & 63;
        tile[k][o] = __float2half(
            __ldg(lut + (size_t)(o0 + o) * KGLOB + k0 + k));
    }
    __syncthreads();
#pragma unroll
    for (int j = 0; j < 16; ++j) {
        const int flat = j * 256 + tid;
        const int k = flat >> 6;
        const int o = flat & 63;
        g_lutT[(size_t)(k0 + k) * OUTFEAT + o0 + o] = tile[k][o];
    }
}

// ---------------------------------------------------------------- agg
// Block: 512 threads (16 warps), tile TO=128 outputs x TN=256 rows.
// Double-buffered cp.async staging of lut chunks [128 idx][128 half].
// Gather: lane owns outputs {4*lane .. 4*lane+3}; one LDS.64 per (row, cb);
// half2 group-8 accumulation, fp32 fold per chunk.
__global__ void __launch_bounds__(THREADS, 1) agg_kernel(float* __restrict__ out)
{
    extern __shared__ __align__(16) char smem[];
    const uint32_t sb = smem_u32(smem);

    const int o0   = blockIdx.x * TO;
    const int n0   = blockIdx.y * TN;
    const int tid  = threadIdx.x;
    const int warp = tid >> 5;
    const int lane = tid & 31;
    const int rowbase = n0 + warp * 16;

    const uint32_t lane_byte = (uint32_t)lane * 8;   // LDS.64 base within idx-row

    float acc[16][4];
#pragma unroll
    for (int t = 0; t < 16; ++t)
#pragma unroll
        for (int j = 0; j < 4; ++j) acc[t][j] = 0.0f;

    // Stage chunk ch into buffer buf (2048 x 16B, 4 per thread, coalesced)
#define STAGE(ch, bufbase) do {                                                \
    const int _c0k = (ch) * CCH * KLEAF;                                       \
    _Pragma("unroll")                                                          \
    for (int _i = 0; _i < 4; ++_i) {                                           \
        const int _flat = _i * THREADS + tid;      /* 0..2047 */               \
        const int _idx  = _flat >> 4;                                          \
        const int _pos  = _flat & 15;                                          \
        cp_async16((bufbase) + (uint32_t)_flat * 16,                           \
                   g_lutT + (size_t)(_c0k + _idx) * OUTFEAT + o0 + _pos * 8);  \
    }                                                                          \
    cp_commit();                                                               \
} while (0)

    // Prologue
    STAGE(0, sb);

    for (int ch = 0; ch < NCHUNK; ++ch) {
        __syncthreads();               // prior gather's readers done with next buf
        if (ch + 1 < NCHUNK) {
            STAGE(ch + 1, sb + (uint32_t)((ch + 1) & 1) * BUFB);
            cp_wait1();                // chunk ch's group complete, ch+1 in flight
        } else {
            cp_wait0();
        }
        __syncthreads();               // cp.async fills visible to all warps

        const uint32_t buf = sb + (uint32_t)(ch & 1) * BUFB;
        const uint32_t gbase = buf + lane_byte;
        const int cb0 = ch * CCH;

#pragma unroll
        for (int t = 0; t < 16; ++t) {
            const int row = rowbase + t;
            const uint2 cw = *reinterpret_cast<const uint2*>(
                g_codes + (size_t)row * NCODE + cb0);   // warp-uniform
            __half2 h01 = __float2half2_rn(0.0f);
            __half2 h23 = __float2half2_rn(0.0f);
#pragma unroll
            for (int cc = 0; cc < 8; ++cc) {
                const unsigned int w = (cc < 4) ? cw.x : cw.y;
                // byte (cc&3) of w placed at result byte1 => code*256
                const unsigned int c256 =
                    __byte_perm(w, 0u, 0x4404u | (((unsigned)cc & 3u) << 4));
                uint32_t v0, v1;
                asm volatile("ld.shared.v2.u32 {%0,%1}, [%2];"
                             : "=r"(v0), "=r"(v1)
                             : "r"(gbase + (uint32_t)cc * 4096u + c256));
                h01 = __hadd2(h01, *reinterpret_cast<const __half2*>(&v0));
                h23 = __hadd2(h23, *reinterpret_cast<const __half2*>(&v1));
            }
            const float2 f0 = __half22float2(h01);
            const float2 f1 = __half22float2(h23);
            acc[t][0] += f0.x;
            acc[t][1] += f0.y;
            acc[t][2] += f1.x;
            acc[t][3] += f1.y;
        }
    }

    // Store: lane's 4 outputs contiguous -> STG.128
#pragma unroll
    for (int t = 0; t < 16; ++t) {
        float4 v;
        v.x = acc[t][0]; v.y = acc[t][1]; v.z = acc[t][2]; v.w = acc[t][3];
        *reinterpret_cast<float4*>(
            out + (size_t)(rowbase + t) * OUTFEAT + o0 + 4 * lane) = v;
    }
}

// ---------------------------------------------------------------- launch
extern "C" void kernel_launch(void* const* d_in, const int* in_sizes, int n_in,
                              void* d_out, int out_size)
{
    const float* input = (const float*)d_in[0];
    const int*   dims  = (const int*)  d_in[1];
    const float* thr   = (const float*)d_in[3];
    const float* lut   = (const float*)d_in[5];
    float*       out   = (float*)d_out;
    (void)in_sizes; (void)n_in; (void)out_size;

    cudaFuncSetAttribute(agg_kernel,
                         cudaFuncAttributeMaxDynamicSharedMemorySize, AGG_SMEM);

    encode_kernel<<<NROWS, NCODE>>>(input, dims, thr);

    dim3 tgrid(KGLOB / 64, OUTFEAT / 64);
    transpose_kernel<<<tgrid, 256>>>(lut);

    dim3 grid(OUTFEAT / TO, NROWS / TN);
    agg_kernel<<<grid, THREADS, AGG_SMEM>>>(out);
}